// round 4
// baseline (speedup 1.0000x reference)
#include <cuda_runtime.h>
#include <cstdint>

// YOLO detection decode: x (64, 255, 52, 52) f32 -> out (64, 8112, 85) f32
// v4: v3 + SW128 XOR swizzle on the smem transpose tile.
//   - phase-1 scalar STS banks get scrambled (was 4-way conflicted, stride 1360B)
//   - phase-2 float4 LDS stays conflict-free (swizzle permutes 16B units in-line)
//   - smem padded to a 128B multiple so swizzled addresses stay in bounds

#define G 52
#define GG 2704              // G*G
#define GGV 676              // GG/4 (channel stride in float4)
#define IN_PER_B 689520      // 255*GG
#define NE 85
#define TILE 52
#define QV 13                // TILE/4
#define NV (NE * QV)         // 1105 float4 per tile
#define TILES_PER_PLANE 52   // GG / TILE
#define THREADS 256
#define SMEM_BYTES 17792     // TILE*NE*4 = 17680, rounded up to 128B multiple

#define SWZ(b) ((b) ^ (((b) >> 3) & 0x70))

__constant__ float c_aw[3] = {10.0f, 16.0f, 33.0f};
__constant__ float c_ah[3] = {13.0f, 30.0f, 23.0f};

__device__ __forceinline__ float fsigmoid(float v) {
    return __fdividef(1.0f, 1.0f + __expf(-v));
}

__global__ __launch_bounds__(THREADS)
void det_decode_kernel(const float* __restrict__ x, float* __restrict__ out) {
    __shared__ alignas(128) char smem[SMEM_BYTES];

    // Tile -> (b, a, p0). tiles/anchor = 52, tiles/batch = 156.
    const int t   = blockIdx.x;
    const int b   = t / 156;
    const int rem = t - b * 156;
    const int a   = rem / TILES_PER_PLANE;
    const int pt  = rem - a * TILES_PER_PLANE;
    const int p0  = pt * TILE;       // spatial offset within the (b,a) plane

    const float4* __restrict__ src = reinterpret_cast<const float4*>(
        x + (size_t)b * IN_PER_B + (size_t)(a * NE) * GG + p0);

    const float aw = c_aw[a];
    const float ah = c_ah[a];

    // Phase 1: load-transform-stage (transposed, swizzled).
    #pragma unroll 4
    for (int j = threadIdx.x; j < NV; j += THREADS) {
        const int e = j / QV;            // channel 0..84
        const int q = j - e * QV;        // float4 index within channel
        const float4 v = __ldcs(src + e * GGV + q);
        const int lp = q * 4;            // local row of component .x

        float o0, o1, o2, o3;
        if (e >= 4) {
            o0 = fsigmoid(v.x); o1 = fsigmoid(v.y);
            o2 = fsigmoid(v.z); o3 = fsigmoid(v.w);
        } else if (e == 0) {
            const int p = p0 + lp;
            o0 = (fsigmoid(v.x) + (float)((p    ) % G)) * 8.0f;
            o1 = (fsigmoid(v.y) + (float)((p + 1) % G)) * 8.0f;
            o2 = (fsigmoid(v.z) + (float)((p + 2) % G)) * 8.0f;
            o3 = (fsigmoid(v.w) + (float)((p + 3) % G)) * 8.0f;
        } else if (e == 1) {
            const int p = p0 + lp;
            o0 = (fsigmoid(v.x) + (float)((p    ) / G)) * 8.0f;
            o1 = (fsigmoid(v.y) + (float)((p + 1) / G)) * 8.0f;
            o2 = (fsigmoid(v.z) + (float)((p + 2) / G)) * 8.0f;
            o3 = (fsigmoid(v.w) + (float)((p + 3) / G)) * 8.0f;
        } else if (e == 2) {
            o0 = __expf(v.x) * aw; o1 = __expf(v.y) * aw;
            o2 = __expf(v.z) * aw; o3 = __expf(v.w) * aw;
        } else { // e == 3
            o0 = __expf(v.x) * ah; o1 = __expf(v.y) * ah;
            o2 = __expf(v.z) * ah; o3 = __expf(v.w) * ah;
        }

        // transpose into swizzled smem: word (lp+k)*NE + e
        uint32_t byte = (uint32_t)(lp * NE + e) << 2;
        *reinterpret_cast<float*>(smem + SWZ(byte)) = o0; byte += NE * 4;
        *reinterpret_cast<float*>(smem + SWZ(byte)) = o1; byte += NE * 4;
        *reinterpret_cast<float*>(smem + SWZ(byte)) = o2; byte += NE * 4;
        *reinterpret_cast<float*>(smem + SWZ(byte)) = o3;
    }

    __syncthreads();

    // Phase 2: tile's output is one contiguous span of TILE*NE = 4420 floats.
    float4* __restrict__ dst =
        reinterpret_cast<float4*>(out + (size_t)t * (TILE * NE));
    #pragma unroll 4
    for (int j = threadIdx.x; j < NV; j += THREADS) {
        const uint32_t byte = (uint32_t)j << 4;
        const float4 v = *reinterpret_cast<const float4*>(smem + SWZ(byte));
        __stcs(dst + j, v);
    }
}

extern "C" void kernel_launch(void* const* d_in, const int* in_sizes, int n_in,
                              void* d_out, int out_size) {
    const float* x = (const float*)d_in[0];
    float* out = (float*)d_out;
    const int blocks = out_size / (TILE * NE);   // 9984
    det_decode_kernel<<<blocks, THREADS>>>(x, out);
}